// round 2
// baseline (speedup 1.0000x reference)
#include <cuda_runtime.h>
#include <cstdint>

// Problem constants (fixed by the reference)
#define BSESS 1024   // sessions (B)
#define NNODE 32     // nodes per session (N)
#define SLEN  50     // steps per session (S)
#define HD    256    // hidden (H)
#define VOC   50000  // vocab (V)

// Scratch (static __device__ — no allocation allowed)
__device__ float g_x[BSESS*HD];
__device__ float g_t[BSESS*HD];
__device__ float g_attn[BSESS*HD];
__device__ float g_cat[BSESS*2*HD];
__device__ float g_sh[BSESS*HD];

// ---------------------------------------------------------------------------
// v_n: only the LAST step of each session matters.
// sections[b]==32, offsets[b]==32*b, last step t = b*S + S-1.
// gidx == 32 -> padded zero row.
// Also seeds g_x (SAN input) and the first half of g_cat.
// ---------------------------------------------------------------------------
__global__ void vn_kernel(const float* __restrict__ node_emb,
                          const float* __restrict__ itemset_len,
                          const int*   __restrict__ sequence) {
    int b = blockIdx.x, h = threadIdx.x;
    int t = b*SLEN + (SLEN-1);
    float acc = 0.f;
    #pragma unroll
    for (int g = 0; g < 3; g++) {
        int s = sequence[t*3 + g];
        if (s != NNODE) acc += node_emb[((size_t)(b*NNODE + s))*HD + h];
    }
    float v = acc / itemset_len[t];
    g_x[b*HD + h] = v;
    g_cat[b*(2*HD) + h] = v;
}

__global__ void cat_kernel() {
    int b = blockIdx.x, h = threadIdx.x;
    g_cat[b*(2*HD) + HD + h] = g_x[b*HD + h];
}

// ---------------------------------------------------------------------------
// Small GEMM: C[M,N] = A[M,K] @ B[N,K]^T + bias[n]; optional ReLU; optional
// elementwise add of addsrc. 64x64 tile, 256 threads, 4x4 per thread.
// M,N multiples of 64; K multiple of 16 (guaranteed here).
// ---------------------------------------------------------------------------
template<bool RELU, bool ADDSRC>
__global__ void gemm_tn_64(const float* __restrict__ A,
                           const float* __restrict__ Bw,
                           const float* __restrict__ bias,
                           const float* __restrict__ addsrc,
                           float* __restrict__ C,
                           int M, int N, int K) {
    __shared__ float As[16][68];
    __shared__ float Bs[16][68];
    int tid = threadIdx.x;
    int m0 = blockIdx.y*64, n0 = blockIdx.x*64;
    int lrow = tid >> 2;
    int kseg = (tid & 3) * 4;
    int ty = tid >> 4, tx = tid & 15;
    float acc[4][4] = {};
    for (int kk = 0; kk < K; kk += 16) {
        float4 av = *(const float4*)&A [((size_t)(m0+lrow))*K + kk + kseg];
        float4 bv = *(const float4*)&Bw[((size_t)(n0+lrow))*K + kk + kseg];
        As[kseg+0][lrow]=av.x; As[kseg+1][lrow]=av.y; As[kseg+2][lrow]=av.z; As[kseg+3][lrow]=av.w;
        Bs[kseg+0][lrow]=bv.x; Bs[kseg+1][lrow]=bv.y; Bs[kseg+2][lrow]=bv.z; Bs[kseg+3][lrow]=bv.w;
        __syncthreads();
        #pragma unroll
        for (int k = 0; k < 16; k++) {
            float4 a = *(const float4*)&As[k][ty*4];
            float4 b = *(const float4*)&Bs[k][tx*4];
            float ar[4] = {a.x, a.y, a.z, a.w};
            float br[4] = {b.x, b.y, b.z, b.w};
            #pragma unroll
            for (int i = 0; i < 4; i++)
                #pragma unroll
                for (int j = 0; j < 4; j++)
                    acc[i][j] += ar[i]*br[j];
        }
        __syncthreads();
    }
    #pragma unroll
    for (int i = 0; i < 4; i++) {
        int gm = m0 + ty*4 + i;
        #pragma unroll
        for (int j = 0; j < 4; j++) {
            int gn = n0 + tx*4 + j;
            float v = acc[i][j] + bias[gn];
            if (RELU)   v = fmaxf(v, 0.f);
            if (ADDSRC) v += addsrc[(size_t)gm*N + gn];
            C[(size_t)gm*N + gn] = v;
        }
    }
}

// ---------------------------------------------------------------------------
// Big GEMM: all_scores[1024,50000] = s_h[1024,256] @ emb_weight[50000,256]^T.
// 128x128 tile, 256 threads, 8x8 per thread. N-bounds guarded (50000 % 128 != 0).
// ---------------------------------------------------------------------------
__global__ void gemm_tn_128(const float* __restrict__ A,
                            const float* __restrict__ Bw,
                            float* __restrict__ C,
                            int M, int N, int K) {
    __shared__ float As[16][132];
    __shared__ float Bs[16][132];
    int tid = threadIdx.x;
    int m0 = blockIdx.y*128, n0 = blockIdx.x*128;
    int ty = tid >> 4, tx = tid & 15;
    float acc[8][8] = {};
    for (int kk = 0; kk < K; kk += 16) {
        #pragma unroll
        for (int i = 0; i < 2; i++) {
            int q = tid*2 + i;          // 0..511 quads of the 128x16 tile
            int r  = q >> 2;            // tile row 0..127
            int ks = (q & 3) * 4;       // k sub-segment
            float4 av = *(const float4*)&A[((size_t)(m0+r))*K + kk + ks];
            As[ks+0][r]=av.x; As[ks+1][r]=av.y; As[ks+2][r]=av.z; As[ks+3][r]=av.w;
            int nr = n0 + r;
            float4 bv = make_float4(0.f, 0.f, 0.f, 0.f);
            if (nr < N) bv = *(const float4*)&Bw[((size_t)nr)*K + kk + ks];
            Bs[ks+0][r]=bv.x; Bs[ks+1][r]=bv.y; Bs[ks+2][r]=bv.z; Bs[ks+3][r]=bv.w;
        }
        __syncthreads();
        #pragma unroll
        for (int k = 0; k < 16; k++) {
            float ar[8], br[8];
            *(float4*)&ar[0] = *(const float4*)&As[k][ty*8];
            *(float4*)&ar[4] = *(const float4*)&As[k][ty*8 + 4];
            *(float4*)&br[0] = *(const float4*)&Bs[k][tx*8];
            *(float4*)&br[4] = *(const float4*)&Bs[k][tx*8 + 4];
            #pragma unroll
            for (int i = 0; i < 8; i++)
                #pragma unroll
                for (int j = 0; j < 8; j++)
                    acc[i][j] += ar[i]*br[j];
        }
        __syncthreads();
    }
    #pragma unroll
    for (int i = 0; i < 8; i++) {
        int gm = m0 + ty*8 + i;
        #pragma unroll
        for (int j = 0; j < 8; j++) {
            int gn = n0 + tx*8 + j;
            if (gn < N) C[(size_t)gm*N + gn] = acc[i][j];
        }
    }
}

// ---------------------------------------------------------------------------
// y_hat[b] = dot(s_h[b], emb_weight[cue[b]])
// ---------------------------------------------------------------------------
__global__ void yhat_kernel(const float* __restrict__ emb,
                            const int*   __restrict__ cue,
                            float* __restrict__ out) {
    int b = blockIdx.x, tid = threadIdx.x;
    float v = g_sh[b*HD + tid] * emb[((size_t)cue[b])*HD + tid];
    #pragma unroll
    for (int o = 16; o > 0; o >>= 1) v += __shfl_down_sync(0xffffffffu, v, o);
    __shared__ float red[8];
    if ((tid & 31) == 0) red[tid >> 5] = v;
    __syncthreads();
    if (tid == 0) {
        float s = 0.f;
        #pragma unroll
        for (int i = 0; i < 8; i++) s += red[i];
        out[b] = s;
    }
}

// ---------------------------------------------------------------------------
// Cache scratch-symbol addresses once, outside of any graph capture, so the
// captured body of kernel_launch is kernel launches ONLY.
// ---------------------------------------------------------------------------
static float *px = nullptr, *pt = nullptr, *pattn = nullptr,
             *pcat = nullptr, *psh = nullptr;

static void resolve_symbols_once() {
    if (px) return;
    cudaGetSymbolAddress((void**)&px,    g_x);
    cudaGetSymbolAddress((void**)&pt,    g_t);
    cudaGetSymbolAddress((void**)&pattn, g_attn);
    cudaGetSymbolAddress((void**)&pcat,  g_cat);
    cudaGetSymbolAddress((void**)&psh,   g_sh);
}

extern "C" void kernel_launch(void* const* d_in, const int* in_sizes, int n_in,
                              void* d_out, int out_size) {
    const float* node_embedding = (const float*)d_in[0];
    const float* emb_weight     = (const float*)d_in[1];
    const float* itemset_len    = (const float*)d_in[2];
    const float* in_proj_w      = (const float*)d_in[3];
    const float* in_proj_b      = (const float*)d_in[4];
    const float* out_proj_w     = (const float*)d_in[5];
    const float* out_proj_b     = (const float*)d_in[6];
    const float* d1_w           = (const float*)d_in[7];
    const float* d1_b           = (const float*)d_in[8];
    const float* d2_w           = (const float*)d_in[9];
    const float* d2_b           = (const float*)d_in[10];
    const float* W3_w           = (const float*)d_in[11];
    const float* W3_b           = (const float*)d_in[12];
    // d_in[13] = batch (unused: sections are constant 32)
    const int*   sequence       = (const int*)d_in[14];
    // d_in[15] = sequence_len (unused: constant S)
    const int*   cue            = (const int*)d_in[16];

    resolve_symbols_once();

    // v_n (also seeds g_x and first half of g_cat)
    vn_kernel<<<BSESS, HD>>>(node_embedding, itemset_len, sequence);

    // SAN chain: x -> 3 blocks of {attn = (x Wv^T+bv) Wo^T+bo; x = attn + relu(attn d1^T+b1) d2^T+b2}
    const float* Wv = in_proj_w + 2*HD*HD;   // in_proj_w[2H:]
    const float* bv = in_proj_b + 2*HD;
    dim3 gs(HD/64, BSESS/64);                // (4, 16)
    for (int it = 0; it < 3; it++) {
        gemm_tn_64<false,false><<<gs, 256>>>(px,    Wv,         bv,         nullptr, pt,    BSESS, HD, HD);
        gemm_tn_64<false,false><<<gs, 256>>>(pt,    out_proj_w, out_proj_b, nullptr, pattn, BSESS, HD, HD);
        gemm_tn_64<true, false><<<gs, 256>>>(pattn, d1_w,       d1_b,       nullptr, pt,    BSESS, HD, HD);
        gemm_tn_64<false,true ><<<gs, 256>>>(pt,    d2_w,       d2_b,       pattn,   px,    BSESS, HD, HD);
    }

    // s_h = [v_n, x] @ W3^T + b3   (K = 512)
    cat_kernel<<<BSESS, HD>>>();
    gemm_tn_64<false,false><<<gs, 256>>>(pcat, W3_w, W3_b, nullptr, psh, BSESS, HD, 2*HD);

    // Outputs: d_out[0:1024) = y_hat, d_out[1024:) = all_scores (row-major 1024 x 50000)
    float* out = (float*)d_out;
    dim3 gb((VOC + 127)/128, BSESS/128);     // (391, 8)
    gemm_tn_128<<<gb, 256>>>(psh, emb_weight, out + BSESS, BSESS, VOC, HD);
    yhat_kernel<<<BSESS, HD>>>(emb_weight, cue, out);
}

// round 5
// speedup vs baseline: 2.0465x; 2.0465x over previous
#include <cuda_runtime.h>
#include <cuda_bf16.h>
#include <cstdint>

// Problem constants
#define BSESS 1024
#define NNODE 32
#define SLEN  50
#define HD    256
#define VOC   50000

// Scores GEMM config: C[1024,50000] = split-bf16, fused K = 768 (3 terms x 256)
#define KC      64                 // bf16 K per chunk (=128B smem row)
#define NCHUNK  12                 // 768 / 64
#define TILEB   16384              // 128 rows x 128 B
#define STAGE   (2*TILEB)          // A tile + B tile
#define SMEM_SZ (2*STAGE)          // double buffered = 65536

// Scratch
__device__ float g_x[BSESS*HD];
__device__ float g_t[BSESS*HD];
__device__ float g_attn[BSESS*HD];
__device__ float g_cat[BSESS*2*HD];
__device__ float g_sh[BSESS*HD];
__device__ __nv_bfloat16 g_Bh[(size_t)VOC*HD];
__device__ __nv_bfloat16 g_Bl[(size_t)VOC*HD];
__device__ __nv_bfloat16 g_Ah[BSESS*HD];
__device__ __nv_bfloat16 g_Al[BSESS*HD];

// ---------------------------------------------------------------------------
// Helpers (baseline ISA only: cp.async, ldmatrix, mma.sync — all sm_80-safe)
// ---------------------------------------------------------------------------
__device__ __forceinline__ uint32_t smem_u32(const void* p) {
    uint32_t a;
    asm("{ .reg .u64 t; cvta.to.shared.u64 t, %1; cvt.u32.u64 %0, t; }"
        : "=r"(a) : "l"(p));
    return a;
}
__device__ __forceinline__ void cp16(uint32_t dst, const void* src) {
    asm volatile("cp.async.cg.shared.global [%0], [%1], 16;"
                 :: "r"(dst), "l"(src));
}
#define CP_COMMIT() asm volatile("cp.async.commit_group;" ::: "memory")
#define CP_WAIT(n)  asm volatile("cp.async.wait_group %0;" :: "n"(n) : "memory")

__device__ __forceinline__ uint32_t sw128(uint32_t x) {   // SW128 xor swizzle
    return x ^ ((x >> 3) & 0x70);
}
__device__ __forceinline__ void ldsm4(uint32_t* r, uint32_t addr) {
    asm volatile("ldmatrix.sync.aligned.m8n8.x4.shared.b16 {%0,%1,%2,%3}, [%4];"
                 : "=r"(r[0]), "=r"(r[1]), "=r"(r[2]), "=r"(r[3]) : "r"(addr));
}
__device__ __forceinline__ void mma16816(float* c, const uint32_t* a,
                                         const uint32_t* b) {
    asm volatile(
        "mma.sync.aligned.m16n8k16.row.col.f32.bf16.bf16.f32 "
        "{%0,%1,%2,%3}, {%4,%5,%6,%7}, {%8,%9}, {%0,%1,%2,%3};"
        : "+f"(c[0]), "+f"(c[1]), "+f"(c[2]), "+f"(c[3])
        : "r"(a[0]), "r"(a[1]), "r"(a[2]), "r"(a[3]), "r"(b[0]), "r"(b[1]));
}

// ---------------------------------------------------------------------------
// v_n gather (only last step matters) + seed g_x, g_cat
// ---------------------------------------------------------------------------
__global__ void vn_kernel(const float* __restrict__ node_emb,
                          const float* __restrict__ itemset_len,
                          const int*   __restrict__ sequence) {
    int b = blockIdx.x, h = threadIdx.x;
    int t = b*SLEN + (SLEN-1);
    float acc = 0.f;
    #pragma unroll
    for (int g = 0; g < 3; g++) {
        int s = sequence[t*3 + g];
        if (s != NNODE) acc += node_emb[((size_t)(b*NNODE + s))*HD + h];
    }
    float v = acc / itemset_len[t];
    g_x[b*HD + h] = v;
    g_cat[b*(2*HD) + h] = v;
}

__global__ void cat_kernel() {
    int b = blockIdx.x, h = threadIdx.x;
    g_cat[b*(2*HD) + HD + h] = g_x[b*HD + h];
}

// ---------------------------------------------------------------------------
// Small GEMM: 64x32 tile, 256 threads, 2x4 per thread. C = A[M,K] B[N,K]^T + bias
// ---------------------------------------------------------------------------
template<bool RELU, bool ADDSRC>
__global__ void gemm_small(const float* __restrict__ A,
                           const float* __restrict__ Bw,
                           const float* __restrict__ bias,
                           const float* __restrict__ addsrc,
                           float* __restrict__ C,
                           int M, int N, int K) {
    __shared__ float As[16][68];
    __shared__ float Bs[16][36];
    int tid = threadIdx.x;
    int m0 = blockIdx.y*64, n0 = blockIdx.x*32;
    int lrow = tid >> 2, kseg = (tid & 3)*4;
    int ty = tid >> 3, tx = tid & 7;
    float acc[2][4] = {};
    for (int kk = 0; kk < K; kk += 16) {
        float4 av = *(const float4*)&A[((size_t)(m0+lrow))*K + kk + kseg];
        As[kseg+0][lrow]=av.x; As[kseg+1][lrow]=av.y; As[kseg+2][lrow]=av.z; As[kseg+3][lrow]=av.w;
        if (tid < 128) {
            int brow = tid >> 2;
            float4 bv = *(const float4*)&Bw[((size_t)(n0+brow))*K + kk + kseg];
            Bs[kseg+0][brow]=bv.x; Bs[kseg+1][brow]=bv.y; Bs[kseg+2][brow]=bv.z; Bs[kseg+3][brow]=bv.w;
        }
        __syncthreads();
        #pragma unroll
        for (int k = 0; k < 16; k++) {
            float2 a = *(const float2*)&As[k][ty*2];
            float4 b = *(const float4*)&Bs[k][tx*4];
            acc[0][0] += a.x*b.x; acc[0][1] += a.x*b.y; acc[0][2] += a.x*b.z; acc[0][3] += a.x*b.w;
            acc[1][0] += a.y*b.x; acc[1][1] += a.y*b.y; acc[1][2] += a.y*b.z; acc[1][3] += a.y*b.w;
        }
        __syncthreads();
    }
    #pragma unroll
    for (int i = 0; i < 2; i++) {
        int gm = m0 + ty*2 + i;
        #pragma unroll
        for (int j = 0; j < 4; j++) {
            int gn = n0 + tx*4 + j;
            float v = acc[i][j] + bias[gn];
            if (RELU)   v = fmaxf(v, 0.f);
            if (ADDSRC) v += addsrc[(size_t)gm*N + gn];
            C[(size_t)gm*N + gn] = v;
        }
    }
}

// ---------------------------------------------------------------------------
// fp32 -> (bf16 hi, bf16 lo) split
// ---------------------------------------------------------------------------
__global__ void conv_split(const float* __restrict__ src,
                           __nv_bfloat16* __restrict__ hi,
                           __nv_bfloat16* __restrict__ lo, int n4) {
    int i = blockIdx.x*256 + threadIdx.x;
    if (i >= n4) return;
    float4 v = ((const float4*)src)[i];
    __nv_bfloat16 h0 = __float2bfloat16(v.x), h1 = __float2bfloat16(v.y),
                  h2 = __float2bfloat16(v.z), h3 = __float2bfloat16(v.w);
    __nv_bfloat16 l0 = __float2bfloat16(v.x - __bfloat162float(h0));
    __nv_bfloat16 l1 = __float2bfloat16(v.y - __bfloat162float(h1));
    __nv_bfloat16 l2 = __float2bfloat16(v.z - __bfloat162float(h2));
    __nv_bfloat16 l3 = __float2bfloat16(v.w - __bfloat162float(h3));
    ((__nv_bfloat162*)hi)[i*2+0] = __nv_bfloat162(h0, h1);
    ((__nv_bfloat162*)hi)[i*2+1] = __nv_bfloat162(h2, h3);
    ((__nv_bfloat162*)lo)[i*2+0] = __nv_bfloat162(l0, l1);
    ((__nv_bfloat162*)lo)[i*2+1] = __nv_bfloat162(l2, l3);
}

// ---------------------------------------------------------------------------
// Scores GEMM (mma.sync bf16, split-fp32). grid (8 m-tiles, 391 n-tiles).
// CTA 128x128, 8 warps (warp_m = wid>>2 in 0..1, warp_n = wid&3 in 0..3),
// warp tile 64x32. K fused = 12 chunks of 64 bf16: term = kc>>2 selects
// (Ah,Bh) / (Ah,Bl) / (Al,Bh); k0 = (kc&3)*64.
// ---------------------------------------------------------------------------
__global__ void __launch_bounds__(256, 1)
scores_kernel(float* __restrict__ out) {
    extern __shared__ char smem[];
    uint32_t sb = smem_u32(smem);
    int tid = threadIdx.x, lane = tid & 31, wid = tid >> 5;
    int wm = wid >> 2, wn = wid & 3;
    int m0 = blockIdx.x * 128, n0 = blockIdx.y * 128;
    int q = lane >> 3, r8 = lane & 7;

    // ldmatrix per-lane coordinates (within tile)
    uint32_t a_row = (uint32_t)(wm*64 + (q & 1)*8 + r8);   // + mb*16
    uint32_t a_kb  = (uint32_t)((q >> 1) * 16);            // + ks*32
    uint32_t b_row = (uint32_t)(wn*32 + (q >> 1)*8 + r8);  // + nb16*16
    uint32_t b_kb  = (uint32_t)((q & 1) * 16);             // + ks*32

    float c[4][4][4];
    #pragma unroll
    for (int i = 0; i < 4; i++)
        #pragma unroll
        for (int j = 0; j < 4; j++)
            #pragma unroll
            for (int k = 0; k < 4; k++) c[i][j][k] = 0.f;

    // chunk loader: A tile + B tile (row-clamped at VOC edge), SW128 swizzle
    auto load_chunk = [&](int kc, int st) {
        int term = kc >> 2;
        const __nv_bfloat16* Asrc = (term == 2) ? g_Al : g_Ah;
        const __nv_bfloat16* Bsrc = (term == 1) ? g_Bl : g_Bh;
        int k0 = (kc & 3) * KC;
        uint32_t abase = sb + st*STAGE;
        uint32_t bbase = abase + TILEB;
        #pragma unroll
        for (int j = tid; j < 1024; j += 256) {
            int row = j >> 3, seg = j & 7;
            uint32_t off = sw128((uint32_t)(row*128 + seg*16));
            cp16(abase + off, Asrc + (size_t)(m0 + row)*HD + k0 + seg*8);
            int gr = n0 + row; if (gr > VOC-1) gr = VOC-1;
            cp16(bbase + off, Bsrc + (size_t)gr*HD + k0 + seg*8);
        }
    };

    load_chunk(0, 0);
    CP_COMMIT();

    for (int kc = 0; kc < NCHUNK; kc++) {
        int st = kc & 1;
        if (kc + 1 < NCHUNK) {
            load_chunk(kc + 1, st ^ 1);
            CP_COMMIT();
            CP_WAIT(1);
        } else {
            CP_WAIT(0);
        }
        __syncthreads();
        uint32_t abase = sb + st*STAGE, bbase = abase + TILEB;
        #pragma unroll
        for (int ks = 0; ks < 4; ks++) {
            uint32_t a[4][4];
            #pragma unroll
            for (int mb = 0; mb < 4; mb++)
                ldsm4(a[mb], abase + sw128((a_row + mb*16)*128 + a_kb + ks*32));
            uint32_t b[4][2];
            #pragma unroll
            for (int nb = 0; nb < 2; nb++) {
                uint32_t r[4];
                ldsm4(r, bbase + sw128((b_row + nb*16)*128 + b_kb + ks*32));
                b[nb*2+0][0] = r[0]; b[nb*2+0][1] = r[1];
                b[nb*2+1][0] = r[2]; b[nb*2+1][1] = r[3];
            }
            #pragma unroll
            for (int mb = 0; mb < 4; mb++)
                #pragma unroll
                for (int n8 = 0; n8 < 4; n8++)
                    mma16816(c[mb][n8], a[mb], b[n8]);
        }
        __syncthreads();
    }

    // Epilogue: per mma fragment, thread holds rows {g, g+8} x cols (t&3)*2..+1
    #pragma unroll
    for (int mb = 0; mb < 4; mb++) {
        int gr0 = m0 + wm*64 + mb*16 + (lane >> 2);
        #pragma unroll
        for (int n8 = 0; n8 < 4; n8++) {
            int col = n0 + wn*32 + n8*8 + (lane & 3)*2;
            if (col < VOC) {
                *(float2*)&out[(size_t)gr0*VOC + col]     =
                    make_float2(c[mb][n8][0], c[mb][n8][1]);
                *(float2*)&out[(size_t)(gr0+8)*VOC + col] =
                    make_float2(c[mb][n8][2], c[mb][n8][3]);
            }
        }
    }
}

// ---------------------------------------------------------------------------
// y_hat[b] = dot(s_h[b], emb_weight[cue[b]])  (exact fp32 path)
// ---------------------------------------------------------------------------
__global__ void yhat_kernel(const float* __restrict__ emb,
                            const int*   __restrict__ cue,
                            float* __restrict__ out) {
    int b = blockIdx.x, tid = threadIdx.x;
    float v = g_sh[b*HD + tid] * emb[((size_t)cue[b])*HD + tid];
    #pragma unroll
    for (int o = 16; o > 0; o >>= 1) v += __shfl_down_sync(0xffffffffu, v, o);
    __shared__ float red[8];
    if ((tid & 31) == 0) red[tid >> 5] = v;
    __syncthreads();
    if (tid == 0) {
        float s = 0.f;
        #pragma unroll
        for (int i = 0; i < 8; i++) s += red[i];
        out[b] = s;
    }
}

// ---------------------------------------------------------------------------
static float *px, *pt, *pattn, *pcat, *psh;
static __nv_bfloat16 *pBh, *pBl, *pAh, *pAl;
static bool g_init = false;

static void resolve_once() {
    if (g_init) return;
    cudaGetSymbolAddress((void**)&px,    g_x);
    cudaGetSymbolAddress((void**)&pt,    g_t);
    cudaGetSymbolAddress((void**)&pattn, g_attn);
    cudaGetSymbolAddress((void**)&pcat,  g_cat);
    cudaGetSymbolAddress((void**)&psh,   g_sh);
    cudaGetSymbolAddress((void**)&pBh,   g_Bh);
    cudaGetSymbolAddress((void**)&pBl,   g_Bl);
    cudaGetSymbolAddress((void**)&pAh,   g_Ah);
    cudaGetSymbolAddress((void**)&pAl,   g_Al);
    cudaFuncSetAttribute(scores_kernel,
                         cudaFuncAttributeMaxDynamicSharedMemorySize, SMEM_SZ);
    g_init = true;
}

extern "C" void kernel_launch(void* const* d_in, const int* in_sizes, int n_in,
                              void* d_out, int out_size) {
    const float* node_embedding = (const float*)d_in[0];
    const float* emb_weight     = (const float*)d_in[1];
    const float* itemset_len    = (const float*)d_in[2];
    const float* in_proj_w      = (const float*)d_in[3];
    const float* in_proj_b      = (const float*)d_in[4];
    const float* out_proj_w     = (const float*)d_in[5];
    const float* out_proj_b     = (const float*)d_in[6];
    const float* d1_w           = (const float*)d_in[7];
    const float* d1_b           = (const float*)d_in[8];
    const float* d2_w           = (const float*)d_in[9];
    const float* d2_b           = (const float*)d_in[10];
    const float* W3_w           = (const float*)d_in[11];
    const float* W3_b           = (const float*)d_in[12];
    const int*   sequence       = (const int*)d_in[14];
    const int*   cue            = (const int*)d_in[16];

    resolve_once();

    // B-side split (independent of everything else)
    conv_split<<<(VOC*HD/4 + 255)/256, 256>>>(emb_weight, pBh, pBl, VOC*HD/4);

    // v_n
    vn_kernel<<<BSESS, HD>>>(node_embedding, itemset_len, sequence);

    // SAN chain
    const float* Wv = in_proj_w + 2*HD*HD;
    const float* bv = in_proj_b + 2*HD;
    dim3 gs(HD/32, BSESS/64);                // (8, 16) = 128 blocks
    for (int it = 0; it < 3; it++) {
        gemm_small<false,false><<<gs, 256>>>(px,    Wv,         bv,         nullptr, pt,    BSESS, HD, HD);
        gemm_small<false,false><<<gs, 256>>>(pt,    out_proj_w, out_proj_b, nullptr, pattn, BSESS, HD, HD);
        gemm_small<true, false><<<gs, 256>>>(pattn, d1_w,       d1_b,       nullptr, pt,    BSESS, HD, HD);
        gemm_small<false,true ><<<gs, 256>>>(pt,    d2_w,       d2_b,       pattn,   px,    BSESS, HD, HD);
    }

    // s_h = [v_n, x] @ W3^T + b3
    cat_kernel<<<BSESS, HD>>>();
    gemm_small<false,false><<<gs, 256>>>(pcat, W3_w, W3_b, nullptr, psh, BSESS, HD, 2*HD);

    // A-side split
    conv_split<<<(BSESS*HD/4 + 255)/256, 256>>>(psh, pAh, pAl, BSESS*HD/4);

    // Outputs
    float* out = (float*)d_out;
    scores_kernel<<<dim3(8, (VOC + 127)/128), 256, SMEM_SZ>>>(out + BSESS);
    yhat_kernel<<<BSESS, HD>>>(emb_weight, cue, out);
}